// round 14
// baseline (speedup 1.0000x reference)
#include <cuda_runtime.h>
#include <cuda_fp16.h>
#include <stdint.h>

// out[r,o] = tanh(scale(r) * dot(enc_row(r), W[o,:]) + b[o])
//   r = b*128 + m (m = l*4+n, l<32) -> M=4096 ; enc phys row = b*2048 + m
//   K=256, N=256. (Spectral DCT/mask/IDCT collapses to mask*enc since the
//   band mask is independent of the DCT index.)
//
// fp16 HMMA m16n8k16, fp32 accum; A and B single fp16 (rel err ~3.2e-4,
// measured R13; threshold 1e-3).
//
// Round 14: 2 K-chunks of 128 (was 4x64) -> 2 barriers total; 1024 threads
// = 32 warps (8/SMSP) for issue-latency hiding; warp tile 16x16 (8Mx4N):
// 2 ldmatrix.x4 + 2 HMMA per k16. Register-staged pipeline:
//   P(0) C(0) P(1) sync MMA(0) C(1) sync MMA(1) epilogue
// P(1)'s LDGs are in flight across all of MMA(0) -> latency fully hidden.
// smem 96KB (A 64 + B 32), grid (32,4) = 128 CTAs = 1 wave.

#define THREADS 1024
#define OFF_A 0
#define OFF_B 65536
#define DYN_SMEM 98304

static __device__ __forceinline__ uint32_t smem_u32(const void* p) {
    uint32_t a;
    asm("{ .reg .u64 t; cvta.to.shared.u64 t, %1; cvt.u32.u64 %0, t; }"
        : "=r"(a) : "l"(p));
    return a;
}

static __device__ __forceinline__ void ldmx4(uint32_t* r, uint32_t addr) {
    asm volatile("ldmatrix.sync.aligned.m8n8.x4.shared.b16 {%0,%1,%2,%3}, [%4];"
                 : "=r"(r[0]), "=r"(r[1]), "=r"(r[2]), "=r"(r[3]) : "r"(addr));
}

static __device__ __forceinline__ void mma16816(float* c, const uint32_t* a,
                                                uint32_t b0, uint32_t b1) {
    asm volatile(
        "mma.sync.aligned.m16n8k16.row.col.f32.f16.f16.f32 "
        "{%0,%1,%2,%3},{%4,%5,%6,%7},{%8,%9},{%0,%1,%2,%3};"
        : "+f"(c[0]), "+f"(c[1]), "+f"(c[2]), "+f"(c[3])
        : "r"(a[0]), "r"(a[1]), "r"(a[2]), "r"(a[3]), "r"(b0), "r"(b1));
}

static __device__ __forceinline__ float tanh_fast(float x) {
    float e = __expf(2.0f * x);
    return 1.0f - __fdividef(2.0f, e + 1.0f);
}

static __device__ __forceinline__ uint4 cvt8_h(const float4& v0, const float4& v1) {
    __half2 h0 = __floats2half2_rn(v0.x, v0.y);
    __half2 h1 = __floats2half2_rn(v0.z, v0.w);
    __half2 h2 = __floats2half2_rn(v1.x, v1.y);
    __half2 h3 = __floats2half2_rn(v1.z, v1.w);
    return make_uint4(*(uint32_t*)&h0, *(uint32_t*)&h1,
                      *(uint32_t*)&h2, *(uint32_t*)&h3);
}

__global__ __launch_bounds__(THREADS, 1) void spectral_hmma_kernel(
    const float* __restrict__ enc,
    const float* __restrict__ W,
    const float* __restrict__ bias,
    float* __restrict__ out)
{
    extern __shared__ __align__(16) uint8_t dyn[];
    const uint32_t sbase = smem_u32(dyn);

    const int tid = threadIdx.x;
    const int wid = tid >> 5;
    const int lid = tid & 31;
    const int bx = blockIdx.x;   // batch (M=128 rows), 0..31
    const int by = blockIdx.y;   // N tile (64 cols), 0..3

    const float4* __restrict__ encv = (const float4*)enc;
    const float4* __restrict__ Wv   = (const float4*)W;

    // chunk-load geometry: unit = 32B fp32 (2 float4) -> 16B fp16 STS.
    // A chunk (128 rows x 16 units) = 2048 units -> 2/thread;
    // B chunk (64 x 16) = 1024 -> 1/thread.
    int aRowL[2], aU[2];
    #pragma unroll
    for (int s = 0; s < 2; ++s) {
        int g = tid + s * 1024;
        aRowL[s] = g >> 4;              // 0..127
        aU[s]    = g & 15;              // unit within chunk
    }
    const int bRowL = tid >> 4;         // 0..63
    const int bU    = tid & 15;

    float4 sa[2][2], sb[2];

    auto prefetch = [&](int c) {
        #pragma unroll
        for (int s = 0; s < 2; ++s) {
            const float4* p = encv
                + ((size_t)(bx * 2048 + aRowL[s])) * 64 + (c * 16 + aU[s]) * 2;
            sa[s][0] = p[0]; sa[s][1] = p[1];
        }
        const float4* p = Wv
            + ((size_t)(by * 64 + bRowL)) * 64 + (c * 16 + bU) * 2;
        sb[0] = p[0]; sb[1] = p[1];
    };

    auto commit = [&](int c) {
        #pragma unroll
        for (int s = 0; s < 2; ++s) {
            int row = aRowL[s], ck = c * 16 + aU[s];
            uint32_t sw = row * 512 + (((ck ^ (row & 7)) & 31) << 4);
            *(uint4*)(dyn + OFF_A + sw) = cvt8_h(sa[s][0], sa[s][1]);
        }
        int ck = c * 16 + bU;
        uint32_t sw = bRowL * 512 + (((ck ^ (bRowL & 7)) & 31) << 4);
        *(uint4*)(dyn + OFF_B + sw) = cvt8_h(sb[0], sb[1]);
    };

    // ---- warp tiling: 32 warps = 8(M: 16 rows) x 4(N: 16 cols)
    const int wm = wid >> 2;
    const int wn = wid & 3;
    const int rl = lid & 15;
    const int kadd = lid >> 4;

    const int aR = wm * 16 + rl;
    const uint32_t aO = aR * 512;
    const int axr = aR & 7;
    const int bR = wn * 16 + rl;
    const uint32_t bO = bR * 512;
    const int bxr = bR & 7;

    float acc[2][4];
    #pragma unroll
    for (int j = 0; j < 2; ++j)
        #pragma unroll
        for (int q = 0; q < 4; ++q)
            acc[j][q] = 0.f;

    // ---- pipeline: P(0) C(0) P(1) sync MMA(0) C(1) sync MMA(1)
    prefetch(0);
    commit(0);
    prefetch(1);
    __syncthreads();

    #pragma unroll
    for (int c = 0; c < 2; ++c) {
        #pragma unroll
        for (int i = 0; i < 8; ++i) {
            const int ch = (c * 8 + i) * 2 + kadd;
            uint32_t a[4], b[4];
            ldmx4(a, sbase + OFF_A + aO + (((ch ^ axr) & 31) << 4));
            ldmx4(b, sbase + OFF_B + bO + (((ch ^ bxr) & 31) << 4));
            mma16816(acc[0], a, b[0], b[2]);
            mma16816(acc[1], a, b[1], b[3]);
        }
        if (c == 0) {
            commit(1);
            __syncthreads();
        }
    }

    // ---- epilogue: band scale, bias, tanh, store
    const int qr = lid >> 2;
    const int qc = (lid & 3) * 2;
    #pragma unroll
    for (int h = 0; h < 2; ++h) {
        const int m = wm * 16 + h * 8 + qr;      // 0..127
        const int n = m & 3, ls = m >> 2;
        const float scale = (n == 0) ? 1.0f
                          : (n == 1) ? ((ls < 16) ? 0.1f : 1.0f)
                          : 0.1f;
        float* orow = out + ((size_t)(bx * 128 + m)) * 256
                          + by * 64 + wn * 16 + qc;
        const float* brow = bias + by * 64 + wn * 16 + qc;
        #pragma unroll
        for (int nt = 0; nt < 2; ++nt) {
            float2 bb = *(const float2*)(brow + nt * 8);
            float2 o;
            o.x = tanh_fast(fmaf(scale, acc[nt][h * 2 + 0], bb.x));
            o.y = tanh_fast(fmaf(scale, acc[nt][h * 2 + 1], bb.y));
            *(float2*)(orow + nt * 8) = o;
        }
    }
}

extern "C" void kernel_launch(void* const* d_in, const int* in_sizes, int n_in,
                              void* d_out, int out_size) {
    const float* enc  = (const float*)d_in[0];
    const float* W    = (const float*)d_in[1];
    const float* bias = (const float*)d_in[2];
    float* out = (float*)d_out;

    cudaFuncSetAttribute(spectral_hmma_kernel,
                         cudaFuncAttributeMaxDynamicSharedMemorySize, DYN_SMEM);
    dim3 grid(32, 4);
    spectral_hmma_kernel<<<grid, THREADS, DYN_SMEM>>>(enc, W, bias, out);
}

// round 15
// speedup vs baseline: 1.0208x; 1.0208x over previous
#include <cuda_runtime.h>
#include <cuda_fp16.h>
#include <stdint.h>

// out[r,o] = tanh(scale(r) * dot(enc_row(r), W[o,:]) + b[o])
//   r = b*128 + m (m = l*4+n, l<32) -> M=4096 ; enc phys row = b*2048 + m
//   K=256, N=256. (Spectral DCT/mask/IDCT collapses to mask*enc since the
//   band mask is independent of the DCT index.)
//
// fp16 HMMA m16n8k16, fp32 accum; A and B single fp16 (rel err ~3.2e-4).
//
// Round 15: scheduling fixes on the proven structure:
//  - fragment double-buffering: ldsm(i+1) issues before mma(i) -> the
//    ldmatrix->mma short-scoreboard chain (the issue=25% culprit) overlaps
//  - commit(1) STS interleaved inside chunk-0's MMA loop (distinct smem
//    columns -> no hazard); one mid-kernel barrier total
// 512 thr = 16 warps 4(M:32)x4(N:16... wait tile 32x16), 2 K-chunks of 128,
// smem 96KB (A 64 + B 32), grid (32,4) = 1 wave.

#define THREADS 512
#define OFF_A 0
#define OFF_B 65536
#define DYN_SMEM 98304

static __device__ __forceinline__ uint32_t smem_u32(const void* p) {
    uint32_t a;
    asm("{ .reg .u64 t; cvta.to.shared.u64 t, %1; cvt.u32.u64 %0, t; }"
        : "=r"(a) : "l"(p));
    return a;
}

static __device__ __forceinline__ void ldmx4(uint32_t* r, uint32_t addr) {
    asm volatile("ldmatrix.sync.aligned.m8n8.x4.shared.b16 {%0,%1,%2,%3}, [%4];"
                 : "=r"(r[0]), "=r"(r[1]), "=r"(r[2]), "=r"(r[3]) : "r"(addr));
}

static __device__ __forceinline__ void mma16816(float* c, const uint32_t* a,
                                                uint32_t b0, uint32_t b1) {
    asm volatile(
        "mma.sync.aligned.m16n8k16.row.col.f32.f16.f16.f32 "
        "{%0,%1,%2,%3},{%4,%5,%6,%7},{%8,%9},{%0,%1,%2,%3};"
        : "+f"(c[0]), "+f"(c[1]), "+f"(c[2]), "+f"(c[3])
        : "r"(a[0]), "r"(a[1]), "r"(a[2]), "r"(a[3]), "r"(b0), "r"(b1));
}

static __device__ __forceinline__ float tanh_fast(float x) {
    float e = __expf(2.0f * x);
    return 1.0f - __fdividef(2.0f, e + 1.0f);
}

static __device__ __forceinline__ uint4 cvt8_h(const float4& v0, const float4& v1) {
    __half2 h0 = __floats2half2_rn(v0.x, v0.y);
    __half2 h1 = __floats2half2_rn(v0.z, v0.w);
    __half2 h2 = __floats2half2_rn(v1.x, v1.y);
    __half2 h3 = __floats2half2_rn(v1.z, v1.w);
    return make_uint4(*(uint32_t*)&h0, *(uint32_t*)&h1,
                      *(uint32_t*)&h2, *(uint32_t*)&h3);
}

__global__ __launch_bounds__(THREADS, 1) void spectral_hmma_kernel(
    const float* __restrict__ enc,
    const float* __restrict__ W,
    const float* __restrict__ bias,
    float* __restrict__ out)
{
    extern __shared__ __align__(16) uint8_t dyn[];
    const uint32_t sbase = smem_u32(dyn);

    const int tid = threadIdx.x;
    const int wid = tid >> 5;
    const int lid = tid & 31;
    const int bx = blockIdx.x;   // batch (M=128 rows), 0..31
    const int by = blockIdx.y;   // N tile (64 cols), 0..3

    const float4* __restrict__ encv = (const float4*)enc;
    const float4* __restrict__ Wv   = (const float4*)W;

    // chunk-load geometry: unit = 32B fp32 -> 16B fp16 STS.
    // A chunk (128 rows x 16 units) = 2048 -> 4 units/thread;
    // B chunk (64 x 16) = 1024 -> 2 units/thread.
    int aRowL[4], aU[4];
    #pragma unroll
    for (int s = 0; s < 4; ++s) {
        int g = tid + s * 512;
        aRowL[s] = g >> 4;              // 0..127
        aU[s]    = g & 15;
    }
    int bRowL[2], bU[2];
    #pragma unroll
    for (int s = 0; s < 2; ++s) {
        int g = tid + s * 512;
        bRowL[s] = g >> 4;              // 0..63
        bU[s]    = g & 15;
    }

    float4 sa[4][2], sb[2][2];

    auto prefetch = [&](int c) {
        #pragma unroll
        for (int s = 0; s < 4; ++s) {
            const float4* p = encv
                + ((size_t)(bx * 2048 + aRowL[s])) * 64 + (c * 16 + aU[s]) * 2;
            sa[s][0] = p[0]; sa[s][1] = p[1];
        }
        #pragma unroll
        for (int s = 0; s < 2; ++s) {
            const float4* p = Wv
                + ((size_t)(by * 64 + bRowL[s])) * 64 + (c * 16 + bU[s]) * 2;
            sb[s][0] = p[0]; sb[s][1] = p[1];
        }
    };

    auto commit = [&](int c) {
        #pragma unroll
        for (int s = 0; s < 4; ++s) {
            int row = aRowL[s], ck = c * 16 + aU[s];
            uint32_t sw = row * 512 + (((ck ^ (row & 7)) & 31) << 4);
            *(uint4*)(dyn + OFF_A + sw) = cvt8_h(sa[s][0], sa[s][1]);
        }
        #pragma unroll
        for (int s = 0; s < 2; ++s) {
            int row = bRowL[s], ck = c * 16 + bU[s];
            uint32_t sw = row * 512 + (((ck ^ (row & 7)) & 31) << 4);
            *(uint4*)(dyn + OFF_B + sw) = cvt8_h(sb[s][0], sb[s][1]);
        }
    };

    // ---- warp tiling: 16 warps = 4(M: 32 rows) x 4(N: 16 cols)
    const int wm = wid >> 2;
    const int wn = wid & 3;
    const int rl = lid & 15;
    const int kadd = lid >> 4;

    const int aR0 = wm * 32 + rl, aR1 = aR0 + 16;
    const uint32_t aO0 = aR0 * 512, aO1 = aR1 * 512;
    const int ax0 = aR0 & 7, ax1 = aR1 & 7;
    const int bR = wn * 16 + rl;
    const uint32_t bO = bR * 512;
    const int bxr = bR & 7;

    // double-buffered fragments
    uint32_t fa0[2][4], fa1[2][4], fb[2][4];

    auto frag_ld = [&](int t, int pb) {
        const int ch = t * 2 + kadd;
        ldmx4(fa0[pb], sbase + OFF_A + aO0 + (((ch ^ ax0) & 31) << 4));
        ldmx4(fa1[pb], sbase + OFF_A + aO1 + (((ch ^ ax1) & 31) << 4));
        ldmx4(fb[pb],  sbase + OFF_B + bO  + (((ch ^ bxr) & 31) << 4));
    };

    float acc[2][2][4];
    #pragma unroll
    for (int i = 0; i < 2; ++i)
        #pragma unroll
        for (int j = 0; j < 2; ++j)
            #pragma unroll
            for (int q = 0; q < 4; ++q)
                acc[i][j][q] = 0.f;

    auto do_mma = [&](int pb) {
        mma16816(acc[0][0], fa0[pb], fb[pb][0], fb[pb][2]);
        mma16816(acc[0][1], fa0[pb], fb[pb][1], fb[pb][3]);
        mma16816(acc[1][0], fa1[pb], fb[pb][0], fb[pb][2]);
        mma16816(acc[1][1], fa1[pb], fb[pb][1], fb[pb][3]);
    };

    // ---- pipeline: P(0) C(0) P(1) sync | MMA(0)+C(1) | sync | MMA(1)
    prefetch(0);
    commit(0);
    prefetch(1);
    __syncthreads();

    // chunk 0: k16 iters 0..7, fragment-pipelined; commit(1) mid-loop
    frag_ld(0, 0);
    #pragma unroll
    for (int i = 0; i < 8; ++i) {
        if (i < 7) frag_ld(i + 1, (i + 1) & 1);
        do_mma(i & 1);
        if (i == 4) commit(1);   // STS to chunk-1 columns: no hazard
    }
    __syncthreads();

    // chunk 1: k16 iters 8..15
    frag_ld(8, 0);
    #pragma unroll
    for (int i = 8; i < 16; ++i) {
        if (i < 15) frag_ld(i + 1, (i + 1) & 1);
        do_mma(i & 1);
    }

    // ---- epilogue: band scale, bias, tanh, store
    const int qr = lid >> 2;
    const int qc = (lid & 3) * 2;
    #pragma unroll
    for (int mt = 0; mt < 2; ++mt) {
        #pragma unroll
        for (int h = 0; h < 2; ++h) {
            const int m = wm * 32 + mt * 16 + h * 8 + qr;   // 0..127
            const int n = m & 3, ls = m >> 2;
            const float scale = (n == 0) ? 1.0f
                              : (n == 1) ? ((ls < 16) ? 0.1f : 1.0f)
                              : 0.1f;
            float* orow = out + ((size_t)(bx * 128 + m)) * 256
                              + by * 64 + wn * 16 + qc;
            const float* brow = bias + by * 64 + wn * 16 + qc;
            #pragma unroll
            for (int nt = 0; nt < 2; ++nt) {
                float2 bb = *(const float2*)(brow + nt * 8);
                float2 o;
                o.x = tanh_fast(fmaf(scale, acc[mt][nt][h * 2 + 0], bb.x));
                o.y = tanh_fast(fmaf(scale, acc[mt][nt][h * 2 + 1], bb.y));
                *(float2*)(orow + nt * 8) = o;
            }
        }
    }
}

extern "C" void kernel_launch(void* const* d_in, const int* in_sizes, int n_in,
                              void* d_out, int out_size) {
    const float* enc  = (const float*)d_in[0];
    const float* W    = (const float*)d_in[1];
    const float* bias = (const float*)d_in[2];
    float* out = (float*)d_out;

    cudaFuncSetAttribute(spectral_hmma_kernel,
                         cudaFuncAttributeMaxDynamicSharedMemorySize, DYN_SMEM);
    dim3 grid(32, 4);
    spectral_hmma_kernel<<<grid, THREADS, DYN_SMEM>>>(enc, W, bias, out);
}

// round 16
// speedup vs baseline: 1.0239x; 1.0030x over previous
#include <cuda_runtime.h>
#include <cuda_fp16.h>
#include <stdint.h>

// out[r,o] = tanh(scale(r) * dot(enc_row(r), W[o,:]) + b[o])
//   r = b*128 + m (m = l*4+n, l<32) -> M=4096 ; enc phys row = b*2048 + m
//   K=256, N=256. (Spectral DCT/mask/IDCT collapses to mask*enc since the
//   band mask is independent of the DCT index.)
//
// fp16 HMMA m16n8k16, fp32 accum; A and B single fp16 (rel err ~3.2e-4).
//
// Round 16: shorten the single-CTA critical path (grid = 1 wave, so kernel
// time == one CTA's serial latency):
//  - warp tile 32x32 + 2-way K-split: 16 warps = 2(K)x4(M)x2(N);
//    LDSM 384->256 KB/CTA (minimum at 16 warps)
//  - ONE pre-mainloop barrier: both K-chunks committed before it (K-split
//    needs all K resident anyway); all LDGs issued in one max-MLP volley
//  - straight 8-iter mainloop w/ fragment double-buffer; smem reduction of
//    the 2 K-partials into the dead A region; kq=0 warps do the epilogue
// 512 thr, smem 96KB (A 64 + B 32), grid (32,4) = 128 CTAs = 1 wave.

#define THREADS 512
#define OFF_A 0
#define OFF_B 65536
#define DYN_SMEM 98304

static __device__ __forceinline__ uint32_t smem_u32(const void* p) {
    uint32_t a;
    asm("{ .reg .u64 t; cvta.to.shared.u64 t, %1; cvt.u32.u64 %0, t; }"
        : "=r"(a) : "l"(p));
    return a;
}

static __device__ __forceinline__ void ldmx4(uint32_t* r, uint32_t addr) {
    asm volatile("ldmatrix.sync.aligned.m8n8.x4.shared.b16 {%0,%1,%2,%3}, [%4];"
                 : "=r"(r[0]), "=r"(r[1]), "=r"(r[2]), "=r"(r[3]) : "r"(addr));
}

static __device__ __forceinline__ void mma16816(float* c, const uint32_t* a,
                                                uint32_t b0, uint32_t b1) {
    asm volatile(
        "mma.sync.aligned.m16n8k16.row.col.f32.f16.f16.f32 "
        "{%0,%1,%2,%3},{%4,%5,%6,%7},{%8,%9},{%0,%1,%2,%3};"
        : "+f"(c[0]), "+f"(c[1]), "+f"(c[2]), "+f"(c[3])
        : "r"(a[0]), "r"(a[1]), "r"(a[2]), "r"(a[3]), "r"(b0), "r"(b1));
}

static __device__ __forceinline__ float tanh_fast(float x) {
    float e = __expf(2.0f * x);
    return 1.0f - __fdividef(2.0f, e + 1.0f);
}

static __device__ __forceinline__ uint4 cvt8_h(const float4& v0, const float4& v1) {
    __half2 h0 = __floats2half2_rn(v0.x, v0.y);
    __half2 h1 = __floats2half2_rn(v0.z, v0.w);
    __half2 h2 = __floats2half2_rn(v1.x, v1.y);
    __half2 h3 = __floats2half2_rn(v1.z, v1.w);
    return make_uint4(*(uint32_t*)&h0, *(uint32_t*)&h1,
                      *(uint32_t*)&h2, *(uint32_t*)&h3);
}

__global__ __launch_bounds__(THREADS, 1) void spectral_hmma_kernel(
    const float* __restrict__ enc,
    const float* __restrict__ W,
    const float* __restrict__ bias,
    float* __restrict__ out)
{
    extern __shared__ __align__(16) uint8_t dyn[];
    const uint32_t sbase = smem_u32(dyn);

    const int tid = threadIdx.x;
    const int wid = tid >> 5;
    const int lid = tid & 31;
    const int bx = blockIdx.x;   // batch (M=128 rows), 0..31
    const int by = blockIdx.y;   // N tile (64 cols), 0..3

    const float4* __restrict__ encv = (const float4*)enc;
    const float4* __restrict__ Wv   = (const float4*)W;

    // chunk-load geometry: unit = 32B fp32 (2 float4) -> 16B fp16 STS.
    // A chunk (128 rows x 16 units) = 2048 -> 4/thread; B chunk 1024 -> 2.
    int aRowL[4], aU[4];
    #pragma unroll
    for (int s = 0; s < 4; ++s) {
        int g = tid + s * 512;
        aRowL[s] = g >> 4;              // 0..127
        aU[s]    = g & 15;
    }
    int bRowL[2], bU[2];
    #pragma unroll
    for (int s = 0; s < 2; ++s) {
        int g = tid + s * 512;
        bRowL[s] = g >> 4;              // 0..63
        bU[s]    = g & 15;
    }

    float4 sa[4][2], sb[2][2];

    auto prefetch = [&](int c) {
        #pragma unroll
        for (int s = 0; s < 4; ++s) {
            const float4* p = encv
                + ((size_t)(bx * 2048 + aRowL[s])) * 64 + (c * 16 + aU[s]) * 2;
            sa[s][0] = p[0]; sa[s][1] = p[1];
        }
        #pragma unroll
        for (int s = 0; s < 2; ++s) {
            const float4* p = Wv
                + ((size_t)(by * 64 + bRowL[s])) * 64 + (c * 16 + bU[s]) * 2;
            sb[s][0] = p[0]; sb[s][1] = p[1];
        }
    };

    auto commit = [&](int c) {
        #pragma unroll
        for (int s = 0; s < 4; ++s) {
            int row = aRowL[s], ck = c * 16 + aU[s];
            uint32_t sw = row * 512 + (((ck ^ (row & 7)) & 31) << 4);
            *(uint4*)(dyn + OFF_A + sw) = cvt8_h(sa[s][0], sa[s][1]);
        }
        #pragma unroll
        for (int s = 0; s < 2; ++s) {
            int row = bRowL[s], ck = c * 16 + bU[s];
            uint32_t sw = row * 512 + (((ck ^ (row & 7)) & 31) << 4);
            *(uint4*)(dyn + OFF_B + sw) = cvt8_h(sb[s][0], sb[s][1]);
        }
    };

    // ---- warp tiling: 16 warps = 2(Kq: 128) x 4(M: 32 rows) x 2(N: 32 cols)
    const int kq = wid >> 3;
    const int wm = (wid >> 1) & 3;
    const int wn = wid & 1;
    const int rl = lid & 15;
    const int kadd = lid >> 4;

    const int aR0 = wm * 32 + rl, aR1 = aR0 + 16;
    const uint32_t aO0 = aR0 * 512, aO1 = aR1 * 512;
    const int ax0 = aR0 & 7, ax1 = aR1 & 7;
    const int bR0 = wn * 32 + rl, bR1 = bR0 + 16;
    const uint32_t bO0 = bR0 * 512, bO1 = bR1 * 512;
    const int bxr0 = bR0 & 7, bxr1 = bR1 & 7;

    uint32_t fa0[2][4], fa1[2][4], fb0[2][4], fb1[2][4];

    auto frag_ld = [&](int t, int pb) {
        const int ch = t * 2 + kadd;
        ldmx4(fa0[pb], sbase + OFF_A + aO0 + (((ch ^ ax0) & 31) << 4));
        ldmx4(fa1[pb], sbase + OFF_A + aO1 + (((ch ^ ax1) & 31) << 4));
        ldmx4(fb0[pb], sbase + OFF_B + bO0 + (((ch ^ bxr0) & 31) << 4));
        ldmx4(fb1[pb], sbase + OFF_B + bO1 + (((ch ^ bxr1) & 31) << 4));
    };

    float acc[2][4][4];
    #pragma unroll
    for (int i = 0; i < 2; ++i)
        #pragma unroll
        for (int j = 0; j < 4; ++j)
            #pragma unroll
            for (int q = 0; q < 4; ++q)
                acc[i][j][q] = 0.f;

    auto do_mma = [&](int pb) {
        #pragma unroll
        for (int mt = 0; mt < 2; ++mt) {
            const uint32_t* a = mt ? fa1[pb] : fa0[pb];
            mma16816(acc[mt][0], a, fb0[pb][0], fb0[pb][2]);
            mma16816(acc[mt][1], a, fb0[pb][1], fb0[pb][3]);
            mma16816(acc[mt][2], a, fb1[pb][0], fb1[pb][2]);
            mma16816(acc[mt][3], a, fb1[pb][1], fb1[pb][3]);
        }
    };

    // ---- load everything, commit both chunks, ONE barrier
    prefetch(0);
    commit(0);
    prefetch(1);
    commit(1);
    __syncthreads();

    // ---- straight mainloop: this warp's K half, 8 k16 iters, frag-pipelined
    const int t0 = kq * 8;
    frag_ld(t0, 0);
    #pragma unroll
    for (int i = 0; i < 8; ++i) {
        if (i < 7) frag_ld(t0 + i + 1, (i + 1) & 1);
        do_mma(i & 1);
    }

    // ---- K-split reduction via smem (A region is dead now)
    __syncthreads();
    const int qr = lid >> 2;         // 0..7
    const int qc = (lid & 3) * 2;    // 0,2,4,6
    const int pos = wm * 2 + wn;     // 0..7, 4KB slab each

    if (kq == 1) {
        #pragma unroll
        for (int mt = 0; mt < 2; ++mt)
            #pragma unroll
            for (int h = 0; h < 2; ++h)
                #pragma unroll
                for (int nt = 0; nt < 4; ++nt) {
                    int row = mt * 16 + h * 8 + qr;       // 0..31
                    int col = nt * 8 + qc;                // 0..30
                    *(float2*)(dyn + pos * 4096 + row * 128 + col * 4) =
                        make_float2(acc[mt][nt][h * 2 + 0],
                                    acc[mt][nt][h * 2 + 1]);
                }
    }
    __syncthreads();

    // ---- epilogue (kq=0 warps): add partial, band scale, bias, tanh, store
    if (kq == 0) {
        #pragma unroll
        for (int mt = 0; mt < 2; ++mt) {
            #pragma unroll
            for (int h = 0; h < 2; ++h) {
                const int mrow = mt * 16 + h * 8 + qr;    // 0..31 local
                const int m = wm * 32 + mrow;             // 0..127
                const int n = m & 3, ls = m >> 2;
                const float scale = (n == 0) ? 1.0f
                                  : (n == 1) ? ((ls < 16) ? 0.1f : 1.0f)
                                  : 0.1f;
                float* orow = out + ((size_t)(bx * 128 + m)) * 256
                                  + by * 64 + wn * 32 + qc;
                const float* brow = bias + by * 64 + wn * 32 + qc;
                #pragma unroll
                for (int nt = 0; nt < 4; ++nt) {
                    float2 part = *(const float2*)(dyn + pos * 4096
                                       + mrow * 128 + (nt * 8 + qc) * 4);
                    float2 bb = *(const float2*)(brow + nt * 8);
                    float2 o;
                    o.x = tanh_fast(fmaf(scale,
                              acc[mt][nt][h * 2 + 0] + part.x, bb.x));
                    o.y = tanh_fast(fmaf(scale,
                              acc[mt][nt][h * 2 + 1] + part.y, bb.y));
                    *(float2*)(orow + nt * 8) = o;
                }
            }
        }
    }
}

extern "C" void kernel_launch(void* const* d_in, const int* in_sizes, int n_in,
                              void* d_out, int out_size) {
    const float* enc  = (const float*)d_in[0];
    const float* W    = (const float*)d_in[1];
    const float* bias = (const float*)d_in[2];
    float* out = (float*)d_out;

    cudaFuncSetAttribute(spectral_hmma_kernel,
                         cudaFuncAttributeMaxDynamicSharedMemorySize, DYN_SMEM);
    dim3 grid(32, 4);
    spectral_hmma_kernel<<<grid, THREADS, DYN_SMEM>>>(enc, W, bias, out);
}